// round 3
// baseline (speedup 1.0000x reference)
#include <cuda_runtime.h>
#include <math.h>

#define HV 3
#define NV 23
#define LV 35
#define CVAL 64
#define BV 256
#define NN 529
// kA chunking
#define LC 7
#define JC 161   /* LC*NV */
#define JP 164
#define NCHUNK 5
// kG chunking
#define GLC 5
#define GJC 115  /* GLC*NV */
#define GJP 116

// ---- device scratch (static; no runtime allocation) ----
__device__ float g_M[HV * CVAL * CVAL];
__device__ float g_v1[HV * CVAL];
__device__ float g_v2[HV * CVAL];
__device__ float g_cc[HV];
__device__ float g_attraw[BV * HV * NN];
__device__ float g_scale[HV * NN];
__device__ float g_shift[HV * NN];
__device__ float g_A[BV * HV * NN];
__device__ float g_gcn[BV * CVAL * NV * LV];

// =====================================================================
// kP: M_h = W2^T W1 ; v1 = cb2^T W1 ; v2 = cb1^T W2 ; cc = L*<cb1,cb2>
// =====================================================================
__global__ void kP(const float* __restrict__ cw1, const float* __restrict__ cb1,
                   const float* __restrict__ cw2, const float* __restrict__ cb2) {
    int h = blockIdx.x;
    __shared__ float sW1[4096], sW2[4096], sb1[64], sb2[64];
    int tid = threadIdx.x;
    for (int i = tid; i < 4096; i += 256) { sW1[i] = cw1[h * 4096 + i]; sW2[i] = cw2[h * 4096 + i]; }
    if (tid < 64) { sb1[tid] = cb1[h * 64 + tid]; sb2[tid] = cb2[h * 64 + tid]; }
    __syncthreads();
    for (int idx = tid; idx < 4096; idx += 256) {
        int c = idx >> 6, cp = idx & 63;
        float a = 0.f;
        #pragma unroll 8
        for (int o = 0; o < 64; o++) a = fmaf(sW2[o * 64 + c], sW1[o * 64 + cp], a);
        g_M[h * 4096 + idx] = a;
    }
    if (tid < 64) {
        float a1 = 0.f, a2 = 0.f;
        for (int o = 0; o < 64; o++) {
            a1 = fmaf(sb2[o], sW1[o * 64 + tid], a1);
            a2 = fmaf(sb1[o], sW2[o * 64 + tid], a2);
        }
        g_v1[h * 64 + tid] = a1; g_v2[h * 64 + tid] = a2;
    }
    if (tid == 0) {
        float a = 0.f;
        for (int o = 0; o < 64; o++) a = fmaf(sb1[o], sb2[o], a);
        g_cc[h] = (float)LV * a;
    }
}

// =====================================================================
// kA: att_raw[b,h,m,n] = (Gram(x, M x) + t1[n] + t2[m] + cc)/2240
// grid (h=3, b=256), 256 threads, ~109KB dyn smem
// =====================================================================
__global__ void __launch_bounds__(256, 2)
kA(const float* __restrict__ x) {
    extern __shared__ float sm[];
    float* sM    = sm;              // 64*65   = 4160
    float* sx    = sM + 4160;       // 64*164  = 10496
    float* sy    = sx + 10496;      // 10496
    float* sgram = sy + 10496;      // 532
    float* sxsum = sgram + 532;     // 64*24   = 1536
    float* st1   = sxsum + 1536;    // 24
    float* st2   = st1 + 24;        // 24   -> total 27268 floats
    int h = blockIdx.x, b = blockIdx.y;
    int tid = threadIdx.x;

    for (int i = tid; i < 4096; i += 256) sM[(i >> 6) * 65 + (i & 63)] = g_M[h * 4096 + i];
    for (int i = tid; i < 532;  i += 256) sgram[i] = 0.f;
    for (int i = tid; i < 1536; i += 256) sxsum[i] = 0.f;

    int tr = tid >> 4, tc = tid & 15;       // GEMM tile coords
    int tile = tid >> 3, sl = tid & 7;      // Gram tile + 8-way k split
    int m0 = (tile >> 2) * 3, n0 = (tile & 3) * 6;
    const float* xb = x + (size_t)b * (CVAL * NV * LV);

    float ga[3][6];
    #pragma unroll
    for (int i = 0; i < 3; i++)
        #pragma unroll
        for (int j = 0; j < 6; j++) ga[i][j] = 0.f;

    for (int ch = 0; ch < NCHUNK; ch++) {
        int l0 = ch * LC;
        __syncthreads();
        // load x chunk: sx[c][li*23+nn] = x[b,c,nn,l0+li]
        for (int i = tid; i < CVAL * NV; i += 256) {
            int c = i / NV, nn = i - c * NV;
            const float* p = xb + (c * NV + nn) * LV + l0;
            float* q = sx + c * JP + nn;
            #pragma unroll
            for (int li = 0; li < LC; li++) q[li * NV] = p[li];
        }
        __syncthreads();
        // xsum accumulation (same-thread ownership across chunks)
        for (int i = tid; i < CVAL * NV; i += 256) {
            int c = i / NV, nn = i - c * NV;
            float s = 0.f;
            #pragma unroll
            for (int li = 0; li < LC; li++) s += sx[c * JP + li * NV + nn];
            sxsum[c * 24 + nn] += s;
        }
        // sy = M * sx (64 x 161, K=64) with 4x4 register tiles, 3 col-blocks
        for (int cb = 0; cb < 3; cb++) {
            int c0 = cb * 64 + tc;
            float acc[4][4];
            #pragma unroll
            for (int i = 0; i < 4; i++)
                #pragma unroll
                for (int j = 0; j < 4; j++) acc[i][j] = 0.f;
            const float* mrow = sM + (tr * 4) * 65;
            #pragma unroll 4
            for (int k = 0; k < 64; k++) {
                float a0 = mrow[k], a1 = mrow[65 + k], a2 = mrow[130 + k], a3 = mrow[195 + k];
                const float* bx = sx + k * JP + c0;
                float b0 = bx[0], b1 = bx[16], b2 = bx[32], b3 = bx[48];
                acc[0][0] = fmaf(a0, b0, acc[0][0]); acc[0][1] = fmaf(a0, b1, acc[0][1]);
                acc[0][2] = fmaf(a0, b2, acc[0][2]); acc[0][3] = fmaf(a0, b3, acc[0][3]);
                acc[1][0] = fmaf(a1, b0, acc[1][0]); acc[1][1] = fmaf(a1, b1, acc[1][1]);
                acc[1][2] = fmaf(a1, b2, acc[1][2]); acc[1][3] = fmaf(a1, b3, acc[1][3]);
                acc[2][0] = fmaf(a2, b0, acc[2][0]); acc[2][1] = fmaf(a2, b1, acc[2][1]);
                acc[2][2] = fmaf(a2, b2, acc[2][2]); acc[2][3] = fmaf(a2, b3, acc[2][3]);
                acc[3][0] = fmaf(a3, b0, acc[3][0]); acc[3][1] = fmaf(a3, b1, acc[3][1]);
                acc[3][2] = fmaf(a3, b2, acc[3][2]); acc[3][3] = fmaf(a3, b3, acc[3][3]);
            }
            #pragma unroll
            for (int i2 = 0; i2 < 4; i2++)
                #pragma unroll
                for (int j2 = 0; j2 < 4; j2++) {
                    int col = c0 + 16 * j2;
                    if (col < JC) sy[(tr * 4 + i2) * JP + col] = acc[i2][j2];
                }
        }
        __syncthreads();
        // Gram: ga[m,n] += sum_{c,li} sx[c,li,m0+..]*sy[c,li,n0+..], k-split by sl
        for (int c = sl; c < 64; c += 8) {
            #pragma unroll
            for (int li = 0; li < LC; li++) {
                int off = c * JP + li * NV;
                float a0 = sx[off + m0], a1 = sx[off + m0 + 1], a2 = sx[off + m0 + 2];
                float b0 = sy[off + n0],     b1 = sy[off + n0 + 1], b2 = sy[off + n0 + 2];
                float b3 = sy[off + n0 + 3], b4 = sy[off + n0 + 4], b5 = sy[off + n0 + 5];
                ga[0][0] = fmaf(a0, b0, ga[0][0]); ga[0][1] = fmaf(a0, b1, ga[0][1]);
                ga[0][2] = fmaf(a0, b2, ga[0][2]); ga[0][3] = fmaf(a0, b3, ga[0][3]);
                ga[0][4] = fmaf(a0, b4, ga[0][4]); ga[0][5] = fmaf(a0, b5, ga[0][5]);
                ga[1][0] = fmaf(a1, b0, ga[1][0]); ga[1][1] = fmaf(a1, b1, ga[1][1]);
                ga[1][2] = fmaf(a1, b2, ga[1][2]); ga[1][3] = fmaf(a1, b3, ga[1][3]);
                ga[1][4] = fmaf(a1, b4, ga[1][4]); ga[1][5] = fmaf(a1, b5, ga[1][5]);
                ga[2][0] = fmaf(a2, b0, ga[2][0]); ga[2][1] = fmaf(a2, b1, ga[2][1]);
                ga[2][2] = fmaf(a2, b2, ga[2][2]); ga[2][3] = fmaf(a2, b3, ga[2][3]);
                ga[2][4] = fmaf(a2, b4, ga[2][4]); ga[2][5] = fmaf(a2, b5, ga[2][5]);
            }
        }
    }
    // reduce 8-way k-split via shuffles (lanes differ in low 3 bits)
    #pragma unroll
    for (int i2 = 0; i2 < 3; i2++)
        #pragma unroll
        for (int j2 = 0; j2 < 6; j2++) {
            float v = ga[i2][j2];
            v += __shfl_xor_sync(0xffffffffu, v, 1);
            v += __shfl_xor_sync(0xffffffffu, v, 2);
            v += __shfl_xor_sync(0xffffffffu, v, 4);
            if (sl == 0 && (m0 + i2) < NV && (n0 + j2) < NV)
                sgram[(m0 + i2) * NV + (n0 + j2)] = v;
        }
    __syncthreads();
    if (tid < NV) {
        float t = 0.f;
        for (int c = 0; c < 64; c++) t = fmaf(g_v1[h * 64 + c], sxsum[c * 24 + tid], t);
        st1[tid] = t;
    } else if (tid >= 32 && tid < 32 + NV) {
        int m = tid - 32;
        float t = 0.f;
        for (int c = 0; c < 64; c++) t = fmaf(g_v2[h * 64 + c], sxsum[c * 24 + m], t);
        st2[m] = t;
    }
    __syncthreads();
    float cc = g_cc[h];
    float* outp = g_attraw + (size_t)(b * HV + h) * NN;
    for (int p = tid; p < NN; p += 256) {
        int m = p / NV, n = p - m * NV;
        outp[p] = (sgram[p] + st1[n] + st2[m] + cc) * (1.f / 2240.f);
    }
}

// =====================================================================
// kB: BN batch stats over b -> per-feature affine (scale, shift)
// grid 3, 529 threads, coalesced over features, double accumulation
// =====================================================================
__global__ void kB(const float* __restrict__ gamma, const float* __restrict__ beta) {
    int h = blockIdx.x;
    int f = threadIdx.x;   // 0..528
    double s = 0.0, s2 = 0.0;
    for (int b = 0; b < BV; b++) {
        float v = g_attraw[(size_t)(b * HV + h) * NN + f];
        s += v; s2 += (double)v * v;
    }
    double mean = s * (1.0 / BV);
    double var = s2 * (1.0 / BV) - mean * mean;
    float sc = gamma[h * NN + f] / sqrtf((float)var + 1e-5f);
    g_scale[h * NN + f] = sc;
    g_shift[h * NN + f] = beta[h * NN + f] - (float)mean * sc;
}

// =====================================================================
// kC: affine + softmax over m (per column n) + A = A_ske + att + A_adp
// grid (h=3, b=256), 256 threads
// =====================================================================
__global__ void kC(const float* __restrict__ A_ske, const float* __restrict__ att) {
    __shared__ float sz[NN], cs[NV];
    int h = blockIdx.x, b = blockIdx.y, tid = threadIdx.x;
    const float* raw = g_attraw + (size_t)(b * HV + h) * NN;
    for (int p = tid; p < NN; p += 256)
        sz[p] = fmaf(raw[p], g_scale[h * NN + p], g_shift[h * NN + p]);
    __syncthreads();
    if (tid < NV) {
        int n = tid;
        float mx = -1e30f;
        for (int m = 0; m < NV; m++) mx = fmaxf(mx, sz[m * NV + n]);
        float s = 0.f;
        for (int m = 0; m < NV; m++) { float e = expf(sz[m * NV + n] - mx); sz[m * NV + n] = e; s += e; }
        cs[n] = s;
    }
    __syncthreads();
    float* outp = g_A + (size_t)(b * HV + h) * NN;
    for (int p = tid; p < NN; p += 256) {
        int n = p % NV;
        outp[p] = A_ske[h * NN + p] + att[h * NN + p] + sz[p] / cs[n];
    }
}

// =====================================================================
// kG: gcn[b,o,j,l] = sum_h sum_c mw[h,o,c]*(sum_i x[b,c,i,l]*A[b,h,i,j]) + sum_h mb[h,o]
// grid (b=256, chunk=7), 256 threads, ~175KB dyn smem
// =====================================================================
__global__ void __launch_bounds__(256, 1)
kG(const float* __restrict__ x, const float* __restrict__ mw, const float* __restrict__ mb) {
    extern __shared__ float sm[];
    float* sx   = sm;               // 64*116  = 7424
    float* ssup = sx + 7424;        // 192*116 = 22272
    float* sW   = ssup + 22272;     // 192*65  = 12480
    float* sA   = sW + 12480;       // 1587 (+pad) -> 43776 total
    int b = blockIdx.x, ch = blockIdx.y, tid = threadIdx.x;
    int l0 = ch * GLC;
    const float* xb = x + (size_t)b * (CVAL * NV * LV);

    for (int i = tid; i < HV * NN; i += 256) sA[i] = g_A[(size_t)b * (HV * NN) + i];
    // sW[(h*64+c)*65 + o] = mw[h,o,c]  (coalesced global read, padded smem scatter)
    for (int i = tid; i < 12288; i += 256) {
        int h = i >> 12, r = i & 4095, o = r >> 6, c = r & 63;
        sW[(h * 64 + c) * 65 + o] = mw[i];
    }
    // sx[c][li*23+i] = x[b,c,i,l0+li]
    for (int i = tid; i < CVAL * NV; i += 256) {
        int c = i / NV, nn = i - c * NV;
        const float* p = xb + (c * NV + nn) * LV + l0;
        float* q = sx + c * GJP + nn;
        #pragma unroll
        for (int li = 0; li < GLC; li++) q[li * NV] = p[li];
    }
    __syncthreads();
    // supp[(h*64+c)][li*23+j] = sum_i sx[c][li*23+i]*A[h][i*23+j]; 2 c-rows/thread
    for (int tt = tid; tt < 480; tt += 256) {
        int h = tt / 160, r = tt % 160, cp = r / 5, li = r % 5;
        int c0 = cp * 2;
        float acc0[NV], acc1[NV];
        #pragma unroll
        for (int j = 0; j < NV; j++) { acc0[j] = 0.f; acc1[j] = 0.f; }
        const float* x0 = sx + c0 * GJP + li * NV;
        const float* x1 = x0 + GJP;
        const float* Ah = sA + h * NN;
        for (int i = 0; i < NV; i++) {
            float a0 = x0[i], a1 = x1[i];
            const float* Ar = Ah + i * NV;
            #pragma unroll
            for (int j = 0; j < NV; j++) {
                float f = Ar[j];
                acc0[j] = fmaf(a0, f, acc0[j]);
                acc1[j] = fmaf(a1, f, acc1[j]);
            }
        }
        float* s0 = ssup + (h * 64 + c0) * GJP + li * NV;
        #pragma unroll
        for (int j = 0; j < NV; j++) { s0[j] = acc0[j]; s0[GJP + j] = acc1[j]; }
    }
    __syncthreads();
    // head GEMM: out[o, p] = sum_{k=0..191} sW[k][o] * ssup[k][p], 64 x 115
    int tr = tid >> 4, tc = tid & 15;
    float acc[4][8];
    #pragma unroll
    for (int i = 0; i < 4; i++)
        #pragma unroll
        for (int j = 0; j < 8; j++) acc[i][j] = 0.f;
    #pragma unroll 4
    for (int k = 0; k < 192; k++) {
        const float* wr = sW + k * 65 + tr * 4;
        float w0 = wr[0], w1 = wr[1], w2 = wr[2], w3 = wr[3];
        const float* sp = ssup + k * GJP + tc;
        #pragma unroll
        for (int j2 = 0; j2 < 8; j2++) {
            float bb = sp[16 * j2];
            acc[0][j2] = fmaf(w0, bb, acc[0][j2]);
            acc[1][j2] = fmaf(w1, bb, acc[1][j2]);
            acc[2][j2] = fmaf(w2, bb, acc[2][j2]);
            acc[3][j2] = fmaf(w3, bb, acc[3][j2]);
        }
    }
    float mbs[4];
    #pragma unroll
    for (int i2 = 0; i2 < 4; i2++) {
        int o = tr * 4 + i2;
        mbs[i2] = mb[o] + mb[64 + o] + mb[128 + o];
    }
    #pragma unroll
    for (int j2 = 0; j2 < 8; j2++) {
        int p = tc + 16 * j2;
        if (p < GJC) {
            int li = p / NV, j = p - li * NV;
            int l = l0 + li;
            #pragma unroll
            for (int i2 = 0; i2 < 4; i2++) {
                int o = tr * 4 + i2;
                g_gcn[((size_t)(b * 64 + o) * NV + j) * LV + l] = acc[i2][j2] + mbs[i2];
            }
        }
    }
}

// =====================================================================
// kT: out[row, l'] = sum_l gcn[row, l]*wseq[l,l'] + bias[l'];  rows = b*64*23
// grid 1472, 128 threads, 2 rows/thread
// =====================================================================
__global__ void kT(const float* __restrict__ wseq, const float* __restrict__ bias,
                   float* __restrict__ out) {
    __shared__ float sr[256 * LV], sw[LV * 36], sb[LV];
    int tid = threadIdx.x;  // 128
    size_t base = (size_t)blockIdx.x * 256 * LV;
    for (int e = tid; e < 256 * LV; e += 128) sr[e] = g_gcn[base + e];
    for (int e = tid; e < LV * LV; e += 128) sw[(e / LV) * 36 + (e % LV)] = wseq[e];
    if (tid < LV) sb[tid] = bias[tid];
    __syncthreads();
    float r0[LV], r1[LV];
    #pragma unroll
    for (int l = 0; l < LV; l++) { r0[l] = sr[tid * LV + l]; r1[l] = sr[(tid + 128) * LV + l]; }
    #pragma unroll 5
    for (int lp = 0; lp < LV; lp++) {
        float a0 = sb[lp], a1 = a0;
        #pragma unroll
        for (int l = 0; l < LV; l++) {
            float w = sw[l * 36 + lp];
            a0 = fmaf(r0[l], w, a0);
            a1 = fmaf(r1[l], w, a1);
        }
        out[base + (size_t)tid * LV + lp] = a0;
        out[base + (size_t)(tid + 128) * LV + lp] = a1;
    }
}

extern "C" void kernel_launch(void* const* d_in, const int* in_sizes, int n_in,
                              void* d_out, int out_size) {
    const float* x     = (const float*)d_in[0];
    const float* cw1   = (const float*)d_in[1];
    const float* cb1   = (const float*)d_in[2];
    const float* cw2   = (const float*)d_in[3];
    const float* cb2   = (const float*)d_in[4];
    const float* gamma = (const float*)d_in[5];
    const float* beta  = (const float*)d_in[6];
    const float* mw    = (const float*)d_in[7];
    const float* mb    = (const float*)d_in[8];
    const float* att   = (const float*)d_in[9];
    const float* A_ske = (const float*)d_in[10];
    const float* wseq  = (const float*)d_in[11];
    const float* bias  = (const float*)d_in[12];
    float* out = (float*)d_out;

    static bool attr_done = false;
    if (!attr_done) {
        cudaFuncSetAttribute(kA, cudaFuncAttributeMaxDynamicSharedMemorySize, 109072);
        cudaFuncSetAttribute(kG, cudaFuncAttributeMaxDynamicSharedMemorySize, 175104);
        attr_done = true;
    }

    kP<<<HV, 256>>>(cw1, cb1, cw2, cb2);
    kA<<<dim3(HV, BV), 256, 109072>>>(x);
    kB<<<HV, NN>>>(gamma, beta);
    kC<<<dim3(HV, BV), 256>>>(A_ske, att);
    kG<<<dim3(BV, 7), 256, 175104>>>(x, mw, mb);
    kT<<<1472, 128>>>(wseq, bias, out);
}

// round 4
// speedup vs baseline: 1.2460x; 1.2460x over previous
#include <cuda_runtime.h>
#include <math.h>

#define HV 3
#define NV 23
#define LV 35
#define NP 24
#define CVAL 64
#define BV 256
#define NN 529
// kA: chunks of 6 l's, padded col dim 144, row stride 148
#define ALC 6
#define AJ 144
#define AXP 148
#define ANCH 6
// kG: same chunking, row stride 145
#define GXP 145

// ---- device scratch (static) ----
__device__ float g_M[HV * CVAL * CVAL];
__device__ float g_v1[HV * CVAL];
__device__ float g_v2[HV * CVAL];
__device__ float g_cc[HV];
__device__ float g_x2[BV * CVAL * LV * NP];      // [b][c][l][n24]
__device__ float g_attraw[BV * HV * NN];
__device__ float g_scale[HV * NN];
__device__ float g_shift[HV * NN];
__device__ float g_A[BV * HV * NN];
__device__ float g_gcn2[BV * CVAL * LV * NP];    // [b][o][l][j24]

// =====================================================================
// kX: transpose x[b,c,n,l] -> x2[b,c,l,n24] (n=23 slot zero-padded)
// 8 slices of 805 per block
// =====================================================================
__global__ void kX(const float* __restrict__ x) {
    __shared__ float s[8 * 805];
    int tid = threadIdx.x;
    size_t base = (size_t)blockIdx.x * (8 * 805);
    for (int i = tid; i < 8 * 805; i += 256) s[i] = x[base + i];
    __syncthreads();
    size_t obase = (size_t)blockIdx.x * (8 * 840);
    for (int i = tid; i < 8 * 840; i += 256) {
        int sl = i / 840, r = i - sl * 840, l = r / NP, n = r - l * NP;
        g_x2[obase + i] = (n < NV) ? s[sl * 805 + n * LV + l] : 0.f;
    }
}

// =====================================================================
// kP: M_h = W2^T W1 ; v1 = cb2^T W1 ; v2 = cb1^T W2 ; cc = L*<cb1,cb2>
// =====================================================================
__global__ void kP(const float* __restrict__ cw1, const float* __restrict__ cb1,
                   const float* __restrict__ cw2, const float* __restrict__ cb2) {
    int h = blockIdx.x;
    __shared__ float sW1[4096], sW2[4096], sb1[64], sb2[64];
    int tid = threadIdx.x;
    for (int i = tid; i < 4096; i += 256) { sW1[i] = cw1[h * 4096 + i]; sW2[i] = cw2[h * 4096 + i]; }
    if (tid < 64) { sb1[tid] = cb1[h * 64 + tid]; sb2[tid] = cb2[h * 64 + tid]; }
    __syncthreads();
    for (int idx = tid; idx < 4096; idx += 256) {
        int c = idx >> 6, cp = idx & 63;
        float a = 0.f;
        #pragma unroll 8
        for (int o = 0; o < 64; o++) a = fmaf(sW2[o * 64 + c], sW1[o * 64 + cp], a);
        g_M[h * 4096 + idx] = a;
    }
    if (tid < 64) {
        float a1 = 0.f, a2 = 0.f;
        for (int o = 0; o < 64; o++) {
            a1 = fmaf(sb2[o], sW1[o * 64 + tid], a1);
            a2 = fmaf(sb1[o], sW2[o * 64 + tid], a2);
        }
        g_v1[h * 64 + tid] = a1; g_v2[h * 64 + tid] = a2;
    }
    if (tid == 0) {
        float a = 0.f;
        for (int o = 0; o < 64; o++) a = fmaf(sb1[o], sb2[o], a);
        g_cc[h] = (float)LV * a;
    }
}

// =====================================================================
// kA: att_raw[b,h,m,n] = (Gram(x, M x) + t1[n] + t2[m] + cc)/2240
// grid (3, 256), 256 thr, ~100.9KB dyn smem, occ 2
// =====================================================================
__global__ void __launch_bounds__(256, 2)
kA() {
    extern __shared__ float sm[];
    float* sM    = sm;              // 64*65  = 4160
    float* sx    = sM + 4160;       // 64*148 = 9472
    float* sy    = sx + 9472;       // 9472
    float* sgram = sy + 9472;       // 532
    float* sxsum = sgram + 532;     // 1536
    float* st1   = sxsum + 1536;    // 24
    float* st2   = st1 + 24;        // 24  -> 25220 floats
    int h = blockIdx.x, b = blockIdx.y, tid = threadIdx.x;

    for (int i = tid; i < 4096; i += 256) sM[(i >> 6) * 65 + (i & 63)] = g_M[h * 4096 + i];

    int tr = tid >> 4, tc = tid & 15;     // GEMM: 4 rows x 9 cols
    int tile = tid >> 3, sl = tid & 7;    // Gram: 8-way k-split
    int m0 = 3 * (tile >> 2), n0 = 6 * (tile & 3);
    const float* xb = g_x2 + (size_t)b * (CVAL * LV * NP);

    float ga[3][6];
    #pragma unroll
    for (int i = 0; i < 3; i++)
        #pragma unroll
        for (int j = 0; j < 6; j++) ga[i][j] = 0.f;
    float xs[6];
    #pragma unroll
    for (int q = 0; q < 6; q++) xs[q] = 0.f;

    for (int ch = 0; ch < ANCH; ch++) {
        int l0p = ch * AJ;   // l0*24
        __syncthreads();
        // contiguous chunk load (zero-fill beyond l=35)
        for (int i = tid; i < CVAL * AJ; i += 256) {
            int c = i / AJ, p = i - c * AJ;
            int gp = l0p + p;
            sx[c * AXP + p] = (gp < LV * NP) ? xb[c * (LV * NP) + gp] : 0.f;
        }
        __syncthreads();
        // xsum partial (register-held, fixed ownership)
        #pragma unroll
        for (int q = 0; q < 6; q++) {
            int i = tid + 256 * q;
            int c = i / NP, n = i - c * NP;
            float s = 0.f;
            #pragma unroll
            for (int li = 0; li < ALC; li++) s += sx[c * AXP + li * NP + n];
            xs[q] += s;
        }
        // GEMM: sy = M * sx  (64 x 144, K=64), 4x9 register tiles
        {
            float acc[4][9];
            #pragma unroll
            for (int i = 0; i < 4; i++)
                #pragma unroll
                for (int j = 0; j < 9; j++) acc[i][j] = 0.f;
            #pragma unroll 2
            for (int k = 0; k < 64; k++) {
                float a0 = sM[(tr * 4 + 0) * 65 + k];
                float a1 = sM[(tr * 4 + 1) * 65 + k];
                float a2 = sM[(tr * 4 + 2) * 65 + k];
                float a3 = sM[(tr * 4 + 3) * 65 + k];
                const float* bp = sx + k * AXP + tc;
                #pragma unroll
                for (int j = 0; j < 9; j++) {
                    float bb = bp[16 * j];
                    acc[0][j] = fmaf(a0, bb, acc[0][j]);
                    acc[1][j] = fmaf(a1, bb, acc[1][j]);
                    acc[2][j] = fmaf(a2, bb, acc[2][j]);
                    acc[3][j] = fmaf(a3, bb, acc[3][j]);
                }
            }
            #pragma unroll
            for (int i = 0; i < 4; i++)
                #pragma unroll
                for (int j = 0; j < 9; j++)
                    sy[(tr * 4 + i) * AXP + tc + 16 * j] = acc[i][j];
        }
        __syncthreads();
        // Gram accumulate: 3m x 6n tiles, k-split over c (stride 8)
        for (int c = sl; c < 64; c += 8) {
            #pragma unroll
            for (int li = 0; li < ALC; li++) {
                int off = c * AXP + li * NP;
                float a0 = sx[off + m0], a1 = sx[off + m0 + 1], a2 = sx[off + m0 + 2];
                float b0 = sy[off + n0],     b1 = sy[off + n0 + 1], b2 = sy[off + n0 + 2];
                float b3 = sy[off + n0 + 3], b4 = sy[off + n0 + 4], b5 = sy[off + n0 + 5];
                ga[0][0] = fmaf(a0, b0, ga[0][0]); ga[0][1] = fmaf(a0, b1, ga[0][1]);
                ga[0][2] = fmaf(a0, b2, ga[0][2]); ga[0][3] = fmaf(a0, b3, ga[0][3]);
                ga[0][4] = fmaf(a0, b4, ga[0][4]); ga[0][5] = fmaf(a0, b5, ga[0][5]);
                ga[1][0] = fmaf(a1, b0, ga[1][0]); ga[1][1] = fmaf(a1, b1, ga[1][1]);
                ga[1][2] = fmaf(a1, b2, ga[1][2]); ga[1][3] = fmaf(a1, b3, ga[1][3]);
                ga[1][4] = fmaf(a1, b4, ga[1][4]); ga[1][5] = fmaf(a1, b5, ga[1][5]);
                ga[2][0] = fmaf(a2, b0, ga[2][0]); ga[2][1] = fmaf(a2, b1, ga[2][1]);
                ga[2][2] = fmaf(a2, b2, ga[2][2]); ga[2][3] = fmaf(a2, b3, ga[2][3]);
                ga[2][4] = fmaf(a2, b4, ga[2][4]); ga[2][5] = fmaf(a2, b5, ga[2][5]);
            }
        }
    }
    // commit xsum
    #pragma unroll
    for (int q = 0; q < 6; q++) sxsum[tid + 256 * q] = xs[q];
    // reduce k-split (lanes differ in low 3 bits)
    #pragma unroll
    for (int i2 = 0; i2 < 3; i2++)
        #pragma unroll
        for (int j2 = 0; j2 < 6; j2++) {
            float v = ga[i2][j2];
            v += __shfl_xor_sync(0xffffffffu, v, 1);
            v += __shfl_xor_sync(0xffffffffu, v, 2);
            v += __shfl_xor_sync(0xffffffffu, v, 4);
            if (sl == 0 && (m0 + i2) < NV && (n0 + j2) < NV)
                sgram[(m0 + i2) * NV + (n0 + j2)] = v;
        }
    __syncthreads();
    if (tid < NV) {
        float t = 0.f;
        for (int c = 0; c < 64; c++) t = fmaf(g_v1[h * 64 + c], sxsum[c * NP + tid], t);
        st1[tid] = t;
    } else if (tid >= 32 && tid < 32 + NV) {
        int m = tid - 32;
        float t = 0.f;
        for (int c = 0; c < 64; c++) t = fmaf(g_v2[h * 64 + c], sxsum[c * NP + m], t);
        st2[m] = t;
    }
    __syncthreads();
    float cc = g_cc[h];
    float* outp = g_attraw + (size_t)(b * HV + h) * NN;
    for (int p = tid; p < NN; p += 256) {
        int m = p / NV, n = p - m * NV;
        outp[p] = (sgram[p] + st1[n] + st2[m] + cc) * (1.f / 2240.f);
    }
}

// =====================================================================
// kB: BN batch stats -> per-feature affine
// =====================================================================
__global__ void kB(const float* __restrict__ gamma, const float* __restrict__ beta) {
    int h = blockIdx.x;
    int f = threadIdx.x;   // 0..528
    double s = 0.0, s2 = 0.0;
    for (int b = 0; b < BV; b++) {
        float v = g_attraw[(size_t)(b * HV + h) * NN + f];
        s += v; s2 += (double)v * v;
    }
    double mean = s * (1.0 / BV);
    double var = s2 * (1.0 / BV) - mean * mean;
    float sc = gamma[h * NN + f] / sqrtf((float)var + 1e-5f);
    g_scale[h * NN + f] = sc;
    g_shift[h * NN + f] = beta[h * NN + f] - (float)mean * sc;
}

// =====================================================================
// kC: affine + column softmax + A = A_ske + att + A_adp
// =====================================================================
__global__ void kC(const float* __restrict__ A_ske, const float* __restrict__ att) {
    __shared__ float sz[NN], cs[NV];
    int h = blockIdx.x, b = blockIdx.y, tid = threadIdx.x;
    const float* raw = g_attraw + (size_t)(b * HV + h) * NN;
    for (int p = tid; p < NN; p += 256)
        sz[p] = fmaf(raw[p], g_scale[h * NN + p], g_shift[h * NN + p]);
    __syncthreads();
    if (tid < NV) {
        int n = tid;
        float mx = -1e30f;
        for (int m = 0; m < NV; m++) mx = fmaxf(mx, sz[m * NV + n]);
        float s = 0.f;
        for (int m = 0; m < NV; m++) { float e = expf(sz[m * NV + n] - mx); sz[m * NV + n] = e; s += e; }
        cs[n] = s;
    }
    __syncthreads();
    float* outp = g_A + (size_t)(b * HV + h) * NN;
    for (int p = tid; p < NN; p += 256) {
        int n = p % NV;
        outp[p] = A_ske[h * NN + p] + att[h * NN + p] + sz[p] / cs[n];
    }
}

// =====================================================================
// kG: per-head loop: supp_h = x * A_h (per-li GEMMs), acc += W_h^T supp_h
// grid (b=256, ch=6), 256 thr, ~97.3KB dyn smem, occ 2
// gcn2[b,o,l,j24]
// =====================================================================
__global__ void __launch_bounds__(256, 2)
kG(const float* __restrict__ mw, const float* __restrict__ mb) {
    extern __shared__ float sm[];
    float* sx   = sm;               // 64*145 = 9280
    float* ssup = sx + 9280;        // 9280
    float* sW   = ssup + 9280;      // 64*65  = 4160
    float* sA   = sW + 4160;        // 1600   -> 24320 floats
    int b = blockIdx.x, ch = blockIdx.y, tid = threadIdx.x;
    int l0p = ch * AJ;
    const float* xb = g_x2 + (size_t)b * (CVAL * LV * NP);

    for (int i = tid; i < 1600; i += 256)
        sA[i] = (i < HV * NN) ? g_A[(size_t)b * (HV * NN) + i] : 0.f;
    for (int i = tid; i < CVAL * AJ; i += 256) {
        int c = i / AJ, p = i - c * AJ;
        int gp = l0p + p;
        sx[c * GXP + p] = (gp < LV * NP) ? xb[c * (LV * NP) + gp] : 0.f;
    }

    int tr = tid >> 4, tc = tid & 15;
    float acc[4][9];
    #pragma unroll
    for (int i = 0; i < 4; i++) {
        int o = tr * 4 + i;
        float mbs = mb[o] + mb[64 + o] + mb[128 + o];
        #pragma unroll
        for (int j = 0; j < 9; j++) acc[i][j] = mbs;
    }

    for (int h = 0; h < HV; h++) {
        __syncthreads();   // covers initial loads; protects ssup from prev head GEMM readers
        for (int i = tid; i < 4096; i += 256) {
            int o = i >> 6, c = i & 63;
            sW[c * 65 + o] = mw[h * 4096 + i];
        }
        // supp: 384 slots = 6 li * 16 cgroups * 4 jgroups, tile 4c x 6j
        for (int s = tid; s < 384; s += 256) {
            int li = s >> 6, rem = s & 63, cg = rem >> 2, jg = rem & 3;
            int c0 = cg * 4, j0 = jg * 6, base = li * NP;
            float a2[4][6];
            #pragma unroll
            for (int t = 0; t < 4; t++)
                #pragma unroll
                for (int j = 0; j < 6; j++) a2[t][j] = 0.f;
            const float* Ah = sA + h * NN;
            for (int i2 = 0; i2 < NV; i2++) {
                float v0 = sx[(c0 + 0) * GXP + base + i2];
                float v1 = sx[(c0 + 1) * GXP + base + i2];
                float v2 = sx[(c0 + 2) * GXP + base + i2];
                float v3 = sx[(c0 + 3) * GXP + base + i2];
                const float* Ar = Ah + i2 * NV + j0;
                #pragma unroll
                for (int j = 0; j < 6; j++) {
                    float w = Ar[j];
                    a2[0][j] = fmaf(v0, w, a2[0][j]);
                    a2[1][j] = fmaf(v1, w, a2[1][j]);
                    a2[2][j] = fmaf(v2, w, a2[2][j]);
                    a2[3][j] = fmaf(v3, w, a2[3][j]);
                }
            }
            #pragma unroll
            for (int t = 0; t < 4; t++)
                #pragma unroll
                for (int j = 0; j < 6; j++)
                    ssup[(c0 + t) * GXP + base + j0 + j] = a2[t][j];
        }
        __syncthreads();
        // head GEMM accumulate: K=64
        #pragma unroll 2
        for (int k = 0; k < 64; k++) {
            float a0 = sW[k * 65 + tr * 4 + 0];
            float a1 = sW[k * 65 + tr * 4 + 1];
            float a2k = sW[k * 65 + tr * 4 + 2];
            float a3 = sW[k * 65 + tr * 4 + 3];
            const float* bp = ssup + k * GXP + tc;
            #pragma unroll
            for (int j = 0; j < 9; j++) {
                float bb = bp[16 * j];
                acc[0][j] = fmaf(a0, bb, acc[0][j]);
                acc[1][j] = fmaf(a1, bb, acc[1][j]);
                acc[2][j] = fmaf(a2k, bb, acc[2][j]);
                acc[3][j] = fmaf(a3, bb, acc[3][j]);
            }
        }
    }
    // store gcn2
    #pragma unroll
    for (int j2 = 0; j2 < 9; j2++) {
        int col = tc + 16 * j2;
        int li = col / NP, j = col - li * NP;
        int l = ch * ALC + li;
        if (l < LV) {
            #pragma unroll
            for (int i = 0; i < 4; i++) {
                int o = tr * 4 + i;
                g_gcn2[((size_t)(b * 64 + o) * LV + l) * NP + j] = acc[i][j2];
            }
        }
    }
}

// =====================================================================
// kT: out[(b,o,j), l'] = sum_l gcn2[(b,o),l,j]*w[l,l'] + bias[l']
// 8 (b,o) rows per block, 4j x 7l' register tiles, staged coalesced output
// =====================================================================
__global__ void kT(const float* __restrict__ wseq, const float* __restrict__ bias,
                   float* __restrict__ out) {
    extern __shared__ float smT[];
    float* sg = smT;              // 8*840 = 6720
    float* sw = sg + 6720;        // 35*36 = 1260
    float* sb = sw + 1260;        // 40
    float* so = sb + 40;          // 8*805 = 6440  -> 14460 floats
    int tid = threadIdx.x;
    size_t gbase = (size_t)blockIdx.x * (8 * LV * NP);
    for (int i = tid; i < 8 * LV * NP; i += 256) sg[i] = g_gcn2[gbase + i];
    for (int i = tid; i < LV * LV; i += 256) sw[(i / LV) * 36 + (i % LV)] = wseq[i];
    if (tid < LV) sb[tid] = bias[tid];
    __syncthreads();
    if (tid < 240) {
        int pair = tid / 30, r = tid - pair * 30, jg = r / 5, lg = r - jg * 5;
        int j0 = jg * 4, lp0 = lg * 7;
        float a[4][7];
        #pragma unroll
        for (int t = 0; t < 4; t++)
            #pragma unroll
            for (int u = 0; u < 7; u++) a[t][u] = sb[lp0 + u];
        const float* gp = sg + pair * (LV * NP) + j0;
        #pragma unroll 5
        for (int l = 0; l < LV; l++) {
            float g0 = gp[l * NP + 0], g1 = gp[l * NP + 1], g2 = gp[l * NP + 2], g3 = gp[l * NP + 3];
            const float* wr = sw + l * 36 + lp0;
            #pragma unroll
            for (int u = 0; u < 7; u++) {
                float w = wr[u];
                a[0][u] = fmaf(g0, w, a[0][u]);
                a[1][u] = fmaf(g1, w, a[1][u]);
                a[2][u] = fmaf(g2, w, a[2][u]);
                a[3][u] = fmaf(g3, w, a[3][u]);
            }
        }
        #pragma unroll
        for (int t = 0; t < 4; t++) {
            int jj = j0 + t;
            if (jj < NV) {
                #pragma unroll
                for (int u = 0; u < 7; u++)
                    so[pair * 805 + jj * LV + lp0 + u] = a[t][u];
            }
        }
    }
    __syncthreads();
    size_t obase = (size_t)blockIdx.x * (8 * 805);
    for (int i = tid; i < 8 * 805; i += 256) out[obase + i] = so[i];
}

extern "C" void kernel_launch(void* const* d_in, const int* in_sizes, int n_in,
                              void* d_out, int out_size) {
    const float* x     = (const float*)d_in[0];
    const float* cw1   = (const float*)d_in[1];
    const float* cb1   = (const float*)d_in[2];
    const float* cw2   = (const float*)d_in[3];
    const float* cb2   = (const float*)d_in[4];
    const float* gamma = (const float*)d_in[5];
    const float* beta  = (const float*)d_in[6];
    const float* mw    = (const float*)d_in[7];
    const float* mb    = (const float*)d_in[8];
    const float* att   = (const float*)d_in[9];
    const float* A_ske = (const float*)d_in[10];
    const float* wseq  = (const float*)d_in[11];
    const float* bias  = (const float*)d_in[12];
    float* out = (float*)d_out;

    static bool attr_done = false;
    if (!attr_done) {
        cudaFuncSetAttribute(kA, cudaFuncAttributeMaxDynamicSharedMemorySize, 25220 * 4);
        cudaFuncSetAttribute(kG, cudaFuncAttributeMaxDynamicSharedMemorySize, 24320 * 4);
        cudaFuncSetAttribute(kT, cudaFuncAttributeMaxDynamicSharedMemorySize, 14460 * 4);
        attr_done = true;
    }

    kX<<<2048, 256>>>(x);
    kP<<<HV, 256>>>(cw1, cb1, cw2, cb2);
    kA<<<dim3(HV, BV), 256, 25220 * 4>>>();
    kB<<<HV, NN>>>(gamma, beta);
    kC<<<dim3(HV, BV), 256>>>(A_ske, att);
    kG<<<dim3(BV, ANCH), 256, 24320 * 4>>>(mw, mb);
    kT<<<2048, 256, 14460 * 4>>>(wseq, bias, out);
}

// round 5
// speedup vs baseline: 1.4968x; 1.2013x over previous
#include <cuda_runtime.h>
#include <math.h>

#define HV 3
#define NV 23
#define LV 35
#define NP 24
#define CVAL 64
#define BV 256
#define NN 529
// chunking: 6 l's per chunk, logical width 144, padded width 160, stride 164
#define ALC 6
#define AJ 144
#define APW 160
#define AXP 164
#define ANCH 6

// ---- device scratch (static) ----
__device__ float g_M[HV * CVAL * CVAL];
__device__ float g_v1[HV * CVAL];
__device__ float g_v2[HV * CVAL];
__device__ float g_cc[HV];
__device__ float g_x2[BV * CVAL * LV * NP];      // [b][c][l][n24]
__device__ float g_attraw[BV * HV * NN];
__device__ float g_scale[HV * NN];
__device__ float g_shift[HV * NN];
__device__ float g_A[BV * HV * NN];
__device__ float g_gcn2[BV * CVAL * LV * NP];    // [b][o][l][j24]

typedef unsigned long long ull;

__device__ __forceinline__ ull pk2(float v) {
    ull r; asm("mov.b64 %0, {%1, %1};" : "=l"(r) : "f"(v)); return r;
}
__device__ __forceinline__ void upk(ull p, float& lo, float& hi) {
    asm("mov.b64 {%0, %1}, %2;" : "=f"(lo), "=f"(hi) : "l"(p));
}
#define FMA2(acc, a, b) asm("fma.rn.f32x2 %0, %1, %2, %0;" : "+l"(acc) : "l"(a), "l"(b))

// =====================================================================
// kX: transpose x[b,c,n,l] -> x2[b,c,l,n24]
// =====================================================================
__global__ void kX(const float* __restrict__ x) {
    __shared__ float s[8 * 805];
    int tid = threadIdx.x;
    size_t base = (size_t)blockIdx.x * (8 * 805);
    for (int i = tid; i < 8 * 805; i += 256) s[i] = x[base + i];
    __syncthreads();
    size_t obase = (size_t)blockIdx.x * (8 * 840);
    for (int i = tid; i < 8 * 840; i += 256) {
        int sl = i / 840, r = i - sl * 840, l = r / NP, n = r - l * NP;
        g_x2[obase + i] = (n < NV) ? s[sl * 805 + n * LV + l] : 0.f;
    }
}

// =====================================================================
// kP: M_h = W2^T W1 (grid (3,8)); v1/v2/cc in part 0
// =====================================================================
__global__ void kP(const float* __restrict__ cw1, const float* __restrict__ cb1,
                   const float* __restrict__ cw2, const float* __restrict__ cb2) {
    int h = blockIdx.x, part = blockIdx.y, tid = threadIdx.x;
    __shared__ float sW1[4096], sW2[4096], sb1[64], sb2[64];
    for (int i = tid; i < 4096; i += 256) { sW1[i] = cw1[h * 4096 + i]; sW2[i] = cw2[h * 4096 + i]; }
    if (tid < 64) { sb1[tid] = cb1[h * 64 + tid]; sb2[tid] = cb2[h * 64 + tid]; }
    __syncthreads();
    #pragma unroll
    for (int q = 0; q < 2; q++) {
        int idx = part * 512 + q * 256 + tid;
        int c = idx >> 6, cp = idx & 63;
        float a = 0.f;
        #pragma unroll 8
        for (int o = 0; o < 64; o++) a = fmaf(sW2[o * 64 + c], sW1[o * 64 + cp], a);
        g_M[h * 4096 + idx] = a;
    }
    if (part == 0) {
        if (tid < 64) {
            float a1 = 0.f, a2 = 0.f;
            for (int o = 0; o < 64; o++) {
                a1 = fmaf(sb2[o], sW1[o * 64 + tid], a1);
                a2 = fmaf(sb1[o], sW2[o * 64 + tid], a2);
            }
            g_v1[h * 64 + tid] = a1; g_v2[h * 64 + tid] = a2;
        }
        if (tid == 0) {
            float a = 0.f;
            for (int o = 0; o < 64; o++) a = fmaf(sb1[o], sb2[o], a);
            g_cc[h] = (float)LV * a;
        }
    }
}

// =====================================================================
// kA: att_raw = (Gram(x, Mx) + t1[n] + t2[m] + cc)/2240; f32x2 GEMMs
// grid (3,256), 256 thr, 109072B dyn smem, occ 2
// =====================================================================
__global__ void __launch_bounds__(256, 2)
kA() {
    extern __shared__ float sm[];
    float* sM    = sm;              // 64*65  = 4160
    float* sx    = sM + 4160;       // 64*164 = 10496
    float* sy    = sx + 10496;      // 10496
    float* sgram = sy + 10496;      // 532
    float* sxsum = sgram + 532;     // 1536
    float* st1   = sxsum + 1536;    // 24
    float* st2   = st1 + 24;        // 24  -> 27268 floats
    int h = blockIdx.x, b = blockIdx.y, tid = threadIdx.x;

    for (int i = tid; i < 4096; i += 256) sM[(i >> 6) * 65 + (i & 63)] = g_M[h * 4096 + i];

    int tr = tid >> 4, tc = tid & 15;     // GEMM tiling: 4 rows x 5 col-pairs
    int tile = tid >> 3, sl = tid & 7;    // Gram: 8-way k-split
    int m0 = 3 * (tile >> 2), n0 = 6 * (tile & 3);
    const float* xb = g_x2 + (size_t)b * (CVAL * LV * NP);

    ull gacc[3][3];
    #pragma unroll
    for (int i = 0; i < 3; i++)
        #pragma unroll
        for (int j = 0; j < 3; j++) gacc[i][j] = 0ull;
    float xs[6];
    #pragma unroll
    for (int q = 0; q < 6; q++) xs[q] = 0.f;

    for (int ch = 0; ch < ANCH; ch++) {
        int l0p = ch * AJ;
        __syncthreads();
        // coalesced chunk load, zero-pad cols >=144 and beyond l=35
        for (int i = tid; i < CVAL * APW; i += 256) {
            int c = i / APW, p = i - c * APW;
            int gp = l0p + p;
            sx[c * AXP + p] = (p < AJ && gp < LV * NP) ? xb[c * (LV * NP) + gp] : 0.f;
        }
        __syncthreads();
        // xsum partials
        #pragma unroll
        for (int q = 0; q < 6; q++) {
            int i = tid + 256 * q;
            int c = i / NP, n = i - c * NP;
            float s = 0.f;
            #pragma unroll
            for (int li = 0; li < ALC; li++) s += sx[c * AXP + li * NP + n];
            xs[q] += s;
        }
        // GEMM sy = M*sx (64 x 160p, K=64), f32x2: 4 rows x 5 pairs
        {
            ull acc2[4][5];
            #pragma unroll
            for (int i = 0; i < 4; i++)
                #pragma unroll
                for (int j = 0; j < 5; j++) acc2[i][j] = 0ull;
            #pragma unroll 2
            for (int k = 0; k < 64; k++) {
                ull pa0 = pk2(sM[(tr * 4 + 0) * 65 + k]);
                ull pa1 = pk2(sM[(tr * 4 + 1) * 65 + k]);
                ull pa2 = pk2(sM[(tr * 4 + 2) * 65 + k]);
                ull pa3 = pk2(sM[(tr * 4 + 3) * 65 + k]);
                const ull* bp = (const ull*)(sx + k * AXP + 2 * tc);
                #pragma unroll
                for (int j = 0; j < 5; j++) {
                    ull bb = bp[16 * j];
                    FMA2(acc2[0][j], pa0, bb);
                    FMA2(acc2[1][j], pa1, bb);
                    FMA2(acc2[2][j], pa2, bb);
                    FMA2(acc2[3][j], pa3, bb);
                }
            }
            #pragma unroll
            for (int i = 0; i < 4; i++)
                #pragma unroll
                for (int j = 0; j < 5; j++)
                    *(ull*)(sy + (tr * 4 + i) * AXP + 2 * tc + 32 * j) = acc2[i][j];
        }
        __syncthreads();
        // Gram accumulate: 3m x 3 n-pairs, k-split over c
        for (int c = sl; c < 64; c += 8) {
            #pragma unroll
            for (int li = 0; li < ALC; li++) {
                int off = c * AXP + li * NP;
                ull pa0 = pk2(sx[off + m0]);
                ull pa1 = pk2(sx[off + m0 + 1]);
                ull pa2 = pk2(sx[off + m0 + 2]);
                const ull* bp = (const ull*)(sy + off + n0);
                ull b0 = bp[0], b1 = bp[1], b2 = bp[2];
                FMA2(gacc[0][0], pa0, b0); FMA2(gacc[0][1], pa0, b1); FMA2(gacc[0][2], pa0, b2);
                FMA2(gacc[1][0], pa1, b0); FMA2(gacc[1][1], pa1, b1); FMA2(gacc[1][2], pa1, b2);
                FMA2(gacc[2][0], pa2, b0); FMA2(gacc[2][1], pa2, b1); FMA2(gacc[2][2], pa2, b2);
            }
        }
    }
    #pragma unroll
    for (int q = 0; q < 6; q++) sxsum[tid + 256 * q] = xs[q];
    // unpack + shuffle-reduce k-split
    #pragma unroll
    for (int i2 = 0; i2 < 3; i2++)
        #pragma unroll
        for (int p2 = 0; p2 < 3; p2++) {
            float lo, hi;
            upk(gacc[i2][p2], lo, hi);
            lo += __shfl_xor_sync(0xffffffffu, lo, 1);
            lo += __shfl_xor_sync(0xffffffffu, lo, 2);
            lo += __shfl_xor_sync(0xffffffffu, lo, 4);
            hi += __shfl_xor_sync(0xffffffffu, hi, 1);
            hi += __shfl_xor_sync(0xffffffffu, hi, 2);
            hi += __shfl_xor_sync(0xffffffffu, hi, 4);
            if (sl == 0) {
                int m = m0 + i2, n = n0 + 2 * p2;
                if (m < NV && n < NV) sgram[m * NV + n] = lo;
                if (m < NV && n + 1 < NV) sgram[m * NV + n + 1] = hi;
            }
        }
    __syncthreads();
    if (tid < NV) {
        float t = 0.f;
        for (int c = 0; c < 64; c++) t = fmaf(g_v1[h * 64 + c], sxsum[c * NP + tid], t);
        st1[tid] = t;
    } else if (tid >= 32 && tid < 32 + NV) {
        int m = tid - 32;
        float t = 0.f;
        for (int c = 0; c < 64; c++) t = fmaf(g_v2[h * 64 + c], sxsum[c * NP + m], t);
        st2[m] = t;
    }
    __syncthreads();
    float cc = g_cc[h];
    float* outp = g_attraw + (size_t)(b * HV + h) * NN;
    for (int p = tid; p < NN; p += 256) {
        int m = p / NV, n = p - m * NV;
        outp[p] = (sgram[p] + st1[n] + st2[m] + cc) * (1.f / 2240.f);
    }
}

// =====================================================================
// kB: BN batch stats, parallel: grid (3,17), 32 feat x 8 batch-groups
// =====================================================================
__global__ void kB(const float* __restrict__ gamma, const float* __restrict__ beta) {
    __shared__ double ds[256], ds2[256];
    int h = blockIdx.x;
    int fg = threadIdx.x & 31, bg = threadIdx.x >> 5;
    int f = blockIdx.y * 32 + fg;
    double s = 0.0, s2 = 0.0;
    if (f < NN) {
        for (int b = bg; b < BV; b += 8) {
            float v = g_attraw[(size_t)(b * HV + h) * NN + f];
            s += v; s2 += (double)v * v;
        }
    }
    ds[threadIdx.x] = s; ds2[threadIdx.x] = s2;
    __syncthreads();
    if (threadIdx.x < 32 && f < NN) {
        double ts = 0.0, ts2 = 0.0;
        #pragma unroll
        for (int g = 0; g < 8; g++) { ts += ds[fg + 32 * g]; ts2 += ds2[fg + 32 * g]; }
        double mean = ts * (1.0 / BV);
        double var = ts2 * (1.0 / BV) - mean * mean;
        float sc = gamma[h * NN + f] / sqrtf((float)var + 1e-5f);
        g_scale[h * NN + f] = sc;
        g_shift[h * NN + f] = beta[h * NN + f] - (float)mean * sc;
    }
}

// =====================================================================
// kC: affine + column softmax + A assembly
// =====================================================================
__global__ void kC(const float* __restrict__ A_ske, const float* __restrict__ att) {
    __shared__ float sz[NN], cs[NV];
    int h = blockIdx.x, b = blockIdx.y, tid = threadIdx.x;
    const float* raw = g_attraw + (size_t)(b * HV + h) * NN;
    for (int p = tid; p < NN; p += 256)
        sz[p] = fmaf(raw[p], g_scale[h * NN + p], g_shift[h * NN + p]);
    __syncthreads();
    if (tid < NV) {
        int n = tid;
        float mx = -1e30f;
        for (int m = 0; m < NV; m++) mx = fmaxf(mx, sz[m * NV + n]);
        float s = 0.f;
        for (int m = 0; m < NV; m++) { float e = expf(sz[m * NV + n] - mx); sz[m * NV + n] = e; s += e; }
        cs[n] = s;
    }
    __syncthreads();
    float* outp = g_A + (size_t)(b * HV + h) * NN;
    for (int p = tid; p < NN; p += 256) {
        int n = p % NV;
        outp[p] = A_ske[h * NN + p] + att[h * NN + p] + sz[p] / cs[n];
    }
}

// =====================================================================
// kG: per-head: supp = x*A_h, acc += W_h^T supp; f32x2 everywhere
// grid (256,6), 256 thr, 107264B dyn smem, occ 2. out: gcn2[b,o,l,j24]
// =====================================================================
__global__ void __launch_bounds__(256, 2)
kG(const float* __restrict__ mw, const float* __restrict__ mb) {
    extern __shared__ float sm[];
    float* sx   = sm;               // 64*164 = 10496
    float* ssup = sx + 10496;       // 10496
    float* sW   = ssup + 10496;     // 64*65  = 4160
    float* sA2  = sW + 4160;        // 3*23*24 = 1656 (+8) -> 26816 floats
    int b = blockIdx.x, ch = blockIdx.y, tid = threadIdx.x;
    int l0p = ch * AJ;
    const float* xb = g_x2 + (size_t)b * (CVAL * LV * NP);

    for (int i = tid; i < HV * NV * NP; i += 256) {
        int h = i / (NV * NP), r = i - h * (NV * NP), ii = r / NP, j = r - ii * NP;
        sA2[i] = (j < NV) ? g_A[(size_t)b * (HV * NN) + h * NN + ii * NV + j] : 0.f;
    }
    for (int i = tid; i < CVAL * APW; i += 256) {
        int c = i / APW, p = i - c * APW;
        int gp = l0p + p;
        sx[c * AXP + p] = (p < AJ && gp < LV * NP) ? xb[c * (LV * NP) + gp] : 0.f;
    }

    int tr = tid >> 4, tc = tid & 15;
    ull acc2[4][5];
    #pragma unroll
    for (int i = 0; i < 4; i++) {
        int o = tr * 4 + i;
        ull mbs = pk2(mb[o] + mb[64 + o] + mb[128 + o]);
        #pragma unroll
        for (int j = 0; j < 5; j++) acc2[i][j] = mbs;
    }

    for (int h = 0; h < HV; h++) {
        __syncthreads();
        for (int i = tid; i < 4096; i += 256) {
            int o = i >> 6, c = i & 63;
            sW[c * 65 + o] = mw[h * 4096 + i];
        }
        // supp GEMM: 384 slots = 6 li * 16 cg * 4 jg; tile 4c x 3 j-pairs
        for (int s = tid; s < 384; s += 256) {
            int li = s >> 6, rem = s & 63, cg = rem >> 2, jg = rem & 3;
            int c0 = cg * 4, j0 = jg * 6, base = li * NP;
            ull a2[4][3];
            #pragma unroll
            for (int t = 0; t < 4; t++)
                #pragma unroll
                for (int j = 0; j < 3; j++) a2[t][j] = 0ull;
            const float* Ah = sA2 + h * (NV * NP) + j0;
            for (int i2 = 0; i2 < NV; i2++) {
                ull pv0 = pk2(sx[(c0 + 0) * AXP + base + i2]);
                ull pv1 = pk2(sx[(c0 + 1) * AXP + base + i2]);
                ull pv2 = pk2(sx[(c0 + 2) * AXP + base + i2]);
                ull pv3 = pk2(sx[(c0 + 3) * AXP + base + i2]);
                const ull* Ar = (const ull*)(Ah + i2 * NP);
                ull b0 = Ar[0], b1 = Ar[1], b2 = Ar[2];
                FMA2(a2[0][0], pv0, b0); FMA2(a2[0][1], pv0, b1); FMA2(a2[0][2], pv0, b2);
                FMA2(a2[1][0], pv1, b0); FMA2(a2[1][1], pv1, b1); FMA2(a2[1][2], pv1, b2);
                FMA2(a2[2][0], pv2, b0); FMA2(a2[2][1], pv2, b1); FMA2(a2[2][2], pv2, b2);
                FMA2(a2[3][0], pv3, b0); FMA2(a2[3][1], pv3, b1); FMA2(a2[3][2], pv3, b2);
            }
            #pragma unroll
            for (int t = 0; t < 4; t++) {
                ull* dst = (ull*)(ssup + (c0 + t) * AXP + base + j0);
                dst[0] = a2[t][0]; dst[1] = a2[t][1]; dst[2] = a2[t][2];
            }
        }
        __syncthreads();
        // head GEMM accumulate: K=64, f32x2, 4 rows x 5 pairs
        #pragma unroll 2
        for (int k = 0; k < 64; k++) {
            ull pa0 = pk2(sW[k * 65 + tr * 4 + 0]);
            ull pa1 = pk2(sW[k * 65 + tr * 4 + 1]);
            ull pa2 = pk2(sW[k * 65 + tr * 4 + 2]);
            ull pa3 = pk2(sW[k * 65 + tr * 4 + 3]);
            const ull* bp = (const ull*)(ssup + k * AXP + 2 * tc);
            #pragma unroll
            for (int j = 0; j < 5; j++) {
                ull bb = bp[16 * j];
                FMA2(acc2[0][j], pa0, bb);
                FMA2(acc2[1][j], pa1, bb);
                FMA2(acc2[2][j], pa2, bb);
                FMA2(acc2[3][j], pa3, bb);
            }
        }
    }
    // store gcn2 as 64-bit pairs
    #pragma unroll
    for (int jp = 0; jp < 5; jp++) {
        int col = 2 * tc + 32 * jp;
        if (col < AJ) {
            int li = col / NP, j = col - li * NP;
            int l = ch * ALC + li;
            if (l < LV) {
                #pragma unroll
                for (int i = 0; i < 4; i++) {
                    int o = tr * 4 + i;
                    *(ull*)&g_gcn2[((size_t)(b * 64 + o) * LV + l) * NP + j] = acc2[i][jp];
                }
            }
        }
    }
}

// =====================================================================
// kT: out[(b,o,j), l'] = sum_l gcn2[(b,o),l,j]*w[l,l'] + bias[l']
// =====================================================================
__global__ void kT(const float* __restrict__ wseq, const float* __restrict__ bias,
                   float* __restrict__ out) {
    extern __shared__ float smT[];
    float* sg = smT;              // 8*840 = 6720
    float* sw = sg + 6720;        // 35*36 = 1260
    float* sb = sw + 1260;        // 40
    float* so = sb + 40;          // 8*805 = 6440 -> 14460 floats
    int tid = threadIdx.x;
    size_t gbase = (size_t)blockIdx.x * (8 * LV * NP);
    for (int i = tid; i < 8 * LV * NP; i += 256) sg[i] = g_gcn2[gbase + i];
    for (int i = tid; i < LV * LV; i += 256) sw[(i / LV) * 36 + (i % LV)] = wseq[i];
    if (tid < LV) sb[tid] = bias[tid];
    __syncthreads();
    if (tid < 240) {
        int pair = tid / 30, r = tid - pair * 30, jg = r / 5, lg = r - jg * 5;
        int j0 = jg * 4, lp0 = lg * 7;
        float a[4][7];
        #pragma unroll
        for (int t = 0; t < 4; t++)
            #pragma unroll
            for (int u = 0; u < 7; u++) a[t][u] = sb[lp0 + u];
        const float* gp = sg + pair * (LV * NP) + j0;
        #pragma unroll 5
        for (int l = 0; l < LV; l++) {
            float g0 = gp[l * NP + 0], g1 = gp[l * NP + 1], g2 = gp[l * NP + 2], g3 = gp[l * NP + 3];
            const float* wr = sw + l * 36 + lp0;
            #pragma unroll
            for (int u = 0; u < 7; u++) {
                float w = wr[u];
                a[0][u] = fmaf(g0, w, a[0][u]);
                a[1][u] = fmaf(g1, w, a[1][u]);
                a[2][u] = fmaf(g2, w, a[2][u]);
                a[3][u] = fmaf(g3, w, a[3][u]);
            }
        }
        #pragma unroll
        for (int t = 0; t < 4; t++) {
            int jj = j0 + t;
            if (jj < NV) {
                #pragma unroll
                for (int u = 0; u < 7; u++)
                    so[pair * 805 + jj * LV + lp0 + u] = a[t][u];
            }
        }
    }
    __syncthreads();
    size_t obase = (size_t)blockIdx.x * (8 * 805);
    for (int i = tid; i < 8 * 805; i += 256) out[obase + i] = so[i];
}

extern "C" void kernel_launch(void* const* d_in, const int* in_sizes, int n_in,
                              void* d_out, int out_size) {
    const float* x     = (const float*)d_in[0];
    const float* cw1   = (const float*)d_in[1];
    const float* cb1   = (const float*)d_in[2];
    const float* cw2   = (const float*)d_in[3];
    const float* cb2   = (const float*)d_in[4];
    const float* gamma = (const float*)d_in[5];
    const float* beta  = (const float*)d_in[6];
    const float* mw    = (const float*)d_in[7];
    const float* mb    = (const float*)d_in[8];
    const float* att   = (const float*)d_in[9];
    const float* A_ske = (const float*)d_in[10];
    const float* wseq  = (const float*)d_in[11];
    const float* bias  = (const float*)d_in[12];
    float* out = (float*)d_out;

    static bool attr_done = false;
    if (!attr_done) {
        cudaFuncSetAttribute(kA, cudaFuncAttributeMaxDynamicSharedMemorySize, 27268 * 4);
        cudaFuncSetAttribute(kG, cudaFuncAttributeMaxDynamicSharedMemorySize, 26816 * 4);
        cudaFuncSetAttribute(kT, cudaFuncAttributeMaxDynamicSharedMemorySize, 14460 * 4);
        attr_done = true;
    }

    kX<<<2048, 256>>>(x);
    kP<<<dim3(HV, 8), 256>>>(cw1, cb1, cw2, cb2);
    kA<<<dim3(HV, BV), 256, 27268 * 4>>>();
    kB<<<dim3(HV, 17), 256>>>(gamma, beta);
    kC<<<dim3(HV, BV), 256>>>(A_ske, att);
    kG<<<dim3(BV, ANCH), 256, 26816 * 4>>>(mw, mb);
    kT<<<2048, 256, 14460 * 4>>>(wseq, bias, out);
}

// round 6
// speedup vs baseline: 1.5900x; 1.0622x over previous
#include <cuda_runtime.h>
#include <math.h>

#define HV 3
#define NV 23
#define LV 35
#define NP 24
#define CVAL 64
#define BV 256
#define NN 529
// chunking: 4 l's per chunk, width 96, row stride 98, 9 chunks
#define ALC 4
#define AJ 96
#define AXP 98
#define ANCH 9

// ---- device scratch (static) ----
__device__ float g_M[HV * CVAL * CVAL];
__device__ float g_v1[HV * CVAL];
__device__ float g_v2[HV * CVAL];
__device__ float g_cc[HV];
__device__ float g_x2[BV * CVAL * LV * NP];      // [b][c][l][n24]
__device__ float g_attraw[BV * HV * NN];
__device__ float g_scale[HV * NN];
__device__ float g_shift[HV * NN];
__device__ float g_A[BV * HV * NN];
__device__ float g_gcn2[BV * CVAL * LV * NP];    // [b][o][l][j24]

typedef unsigned long long ull;

__device__ __forceinline__ ull pk2(float v) {
    ull r; asm("mov.b64 %0, {%1, %1};" : "=l"(r) : "f"(v)); return r;
}
__device__ __forceinline__ void upk(ull p, float& lo, float& hi) {
    asm("mov.b64 {%0, %1}, %2;" : "=f"(lo), "=f"(hi) : "l"(p));
}
#define FMA2(acc, a, b) asm("fma.rn.f32x2 %0, %1, %2, %0;" : "+l"(acc) : "l"(a), "l"(b))

// =====================================================================
// kX: transpose x[b,c,n,l] -> x2[b,c,l,n24]
// =====================================================================
__global__ void kX(const float* __restrict__ x) {
    __shared__ float s[8 * 805];
    int tid = threadIdx.x;
    size_t base = (size_t)blockIdx.x * (8 * 805);
    for (int i = tid; i < 8 * 805; i += 256) s[i] = x[base + i];
    __syncthreads();
    size_t obase = (size_t)blockIdx.x * (8 * 840);
    for (int i = tid; i < 8 * 840; i += 256) {
        int sl = i / 840, r = i - sl * 840, l = r / NP, n = r - l * NP;
        g_x2[obase + i] = (n < NV) ? s[sl * 805 + n * LV + l] : 0.f;
    }
}

// =====================================================================
// kP: M_h = W2^T W1 (grid (3,8)); v1/v2/cc in part 0
// =====================================================================
__global__ void kP(const float* __restrict__ cw1, const float* __restrict__ cb1,
                   const float* __restrict__ cw2, const float* __restrict__ cb2) {
    int h = blockIdx.x, part = blockIdx.y, tid = threadIdx.x;
    __shared__ float sW1[4096], sW2[4096], sb1[64], sb2[64];
    for (int i = tid; i < 4096; i += 256) { sW1[i] = cw1[h * 4096 + i]; sW2[i] = cw2[h * 4096 + i]; }
    if (tid < 64) { sb1[tid] = cb1[h * 64 + tid]; sb2[tid] = cb2[h * 64 + tid]; }
    __syncthreads();
    #pragma unroll
    for (int q = 0; q < 2; q++) {
        int idx = part * 512 + q * 256 + tid;
        int c = idx >> 6, cp = idx & 63;
        float a = 0.f;
        #pragma unroll 8
        for (int o = 0; o < 64; o++) a = fmaf(sW2[o * 64 + c], sW1[o * 64 + cp], a);
        g_M[h * 4096 + idx] = a;
    }
    if (part == 0) {
        if (tid < 64) {
            float a1 = 0.f, a2 = 0.f;
            for (int o = 0; o < 64; o++) {
                a1 = fmaf(sb2[o], sW1[o * 64 + tid], a1);
                a2 = fmaf(sb1[o], sW2[o * 64 + tid], a2);
            }
            g_v1[h * 64 + tid] = a1; g_v2[h * 64 + tid] = a2;
        }
        if (tid == 0) {
            float a = 0.f;
            for (int o = 0; o < 64; o++) a = fmaf(sb1[o], sb2[o], a);
            g_cc[h] = (float)LV * a;
        }
    }
}

// =====================================================================
// kA: att_raw = (Gram(x, Mx) + t1[n] + t2[m] + cc)/2240
// grid (3,256), 256 thr, 72.96KB dyn smem, occ 3
// sgram/st1/st2 alias sM (dead after last pre-Gram barrier)
// =====================================================================
__global__ void __launch_bounds__(256, 3)
kA() {
    extern __shared__ float sm[];
    float* sM    = sm;              // 64*65 = 4160
    float* sx    = sM + 4160;       // 64*98 = 6272
    float* sy    = sx + 6272;       // 6272
    float* sxsum = sy + 6272;       // 1536  -> 18240 floats total
    float* sgram = sM;              // alias (532)
    float* st1   = sM + 532;        // alias (24)
    float* st2   = sM + 556;        // alias (24)
    int h = blockIdx.x, b = blockIdx.y, tid = threadIdx.x;

    for (int i = tid; i < 4096; i += 256) sM[(i >> 6) * 65 + (i & 63)] = g_M[h * 4096 + i];

    int tr = tid >> 4, tc = tid & 15;     // GEMM: 4 rows x 3 col-pairs
    int tile = tid >> 3, sl = tid & 7;    // Gram: 8-way k-split
    int m0 = 3 * (tile >> 2), n0 = 6 * (tile & 3);
    const float* xb = g_x2 + (size_t)b * (CVAL * LV * NP);

    ull gacc[3][3];
    #pragma unroll
    for (int i = 0; i < 3; i++)
        #pragma unroll
        for (int j = 0; j < 3; j++) gacc[i][j] = 0ull;
    float xs[6];
    #pragma unroll
    for (int q = 0; q < 6; q++) xs[q] = 0.f;

    for (int ch = 0; ch < ANCH; ch++) {
        int l0p = ch * AJ;
        __syncthreads();
        // coalesced chunk load; zero-fill beyond l=35 (chunk 8 tail)
        for (int i = tid; i < CVAL * AJ; i += 256) {
            int c = i / AJ, p = i - c * AJ;
            int gp = l0p + p;
            sx[c * AXP + p] = (gp < LV * NP) ? xb[c * (LV * NP) + gp] : 0.f;
        }
        __syncthreads();
        // xsum partials (fixed thread ownership; zero pads are harmless)
        #pragma unroll
        for (int q = 0; q < 6; q++) {
            int i = tid + 256 * q;
            int c = i / NP, n = i - c * NP;
            float s = 0.f;
            #pragma unroll
            for (int li = 0; li < ALC; li++) s += sx[c * AXP + li * NP + n];
            xs[q] += s;
        }
        // GEMM sy = M*sx (64 x 96, K=64), f32x2: 4 rows x 3 pairs
        {
            ull acc2[4][3];
            #pragma unroll
            for (int i = 0; i < 4; i++)
                #pragma unroll
                for (int j = 0; j < 3; j++) acc2[i][j] = 0ull;
            #pragma unroll 4
            for (int k = 0; k < 64; k++) {
                ull pa0 = pk2(sM[(tr * 4 + 0) * 65 + k]);
                ull pa1 = pk2(sM[(tr * 4 + 1) * 65 + k]);
                ull pa2 = pk2(sM[(tr * 4 + 2) * 65 + k]);
                ull pa3 = pk2(sM[(tr * 4 + 3) * 65 + k]);
                const ull* bp = (const ull*)(sx + k * AXP + 2 * tc);
                #pragma unroll
                for (int j = 0; j < 3; j++) {
                    ull bb = bp[16 * j];
                    FMA2(acc2[0][j], pa0, bb);
                    FMA2(acc2[1][j], pa1, bb);
                    FMA2(acc2[2][j], pa2, bb);
                    FMA2(acc2[3][j], pa3, bb);
                }
            }
            #pragma unroll
            for (int i = 0; i < 4; i++)
                #pragma unroll
                for (int j = 0; j < 3; j++)
                    *(ull*)(sy + (tr * 4 + i) * AXP + 2 * tc + 32 * j) = acc2[i][j];
        }
        __syncthreads();
        // Gram accumulate: 3m x 3 n-pairs, k-split over c
        for (int c = sl; c < 64; c += 8) {
            #pragma unroll
            for (int li = 0; li < ALC; li++) {
                int off = c * AXP + li * NP;
                ull pa0 = pk2(sx[off + m0]);
                ull pa1 = pk2(sx[off + m0 + 1]);
                ull pa2 = pk2(sx[off + m0 + 2]);
                const ull* bp = (const ull*)(sy + off + n0);
                ull b0 = bp[0], b1 = bp[1], b2 = bp[2];
                FMA2(gacc[0][0], pa0, b0); FMA2(gacc[0][1], pa0, b1); FMA2(gacc[0][2], pa0, b2);
                FMA2(gacc[1][0], pa1, b0); FMA2(gacc[1][1], pa1, b1); FMA2(gacc[1][2], pa1, b2);
                FMA2(gacc[2][0], pa2, b0); FMA2(gacc[2][1], pa2, b1); FMA2(gacc[2][2], pa2, b2);
            }
        }
    }
    #pragma unroll
    for (int q = 0; q < 6; q++) sxsum[tid + 256 * q] = xs[q];
    // unpack + shuffle-reduce k-split; write into sgram (aliases sM, now dead)
    #pragma unroll
    for (int i2 = 0; i2 < 3; i2++)
        #pragma unroll
        for (int p2 = 0; p2 < 3; p2++) {
            float lo, hi;
            upk(gacc[i2][p2], lo, hi);
            lo += __shfl_xor_sync(0xffffffffu, lo, 1);
            lo += __shfl_xor_sync(0xffffffffu, lo, 2);
            lo += __shfl_xor_sync(0xffffffffu, lo, 4);
            hi += __shfl_xor_sync(0xffffffffu, hi, 1);
            hi += __shfl_xor_sync(0xffffffffu, hi, 2);
            hi += __shfl_xor_sync(0xffffffffu, hi, 4);
            if (sl == 0) {
                int m = m0 + i2, n = n0 + 2 * p2;
                if (m < NV && n < NV) sgram[m * NV + n] = lo;
                if (m < NV && n + 1 < NV) sgram[m * NV + n + 1] = hi;
            }
        }
    __syncthreads();
    if (tid < NV) {
        float t = 0.f;
        for (int c = 0; c < 64; c++) t = fmaf(g_v1[h * 64 + c], sxsum[c * NP + tid], t);
        st1[tid] = t;
    } else if (tid >= 32 && tid < 32 + NV) {
        int m = tid - 32;
        float t = 0.f;
        for (int c = 0; c < 64; c++) t = fmaf(g_v2[h * 64 + c], sxsum[c * NP + m], t);
        st2[m] = t;
    }
    __syncthreads();
    float cc = g_cc[h];
    float* outp = g_attraw + (size_t)(b * HV + h) * NN;
    for (int p = tid; p < NN; p += 256) {
        int m = p / NV, n = p - m * NV;
        outp[p] = (sgram[p] + st1[n] + st2[m] + cc) * (1.f / 2240.f);
    }
}

// =====================================================================
// kB: BN batch stats, grid (3,17), 512 thr = 32 feat x 16 batch-groups
// =====================================================================
__global__ void kB(const float* __restrict__ gamma, const float* __restrict__ beta) {
    __shared__ double ds[512], ds2[512];
    int h = blockIdx.x;
    int fg = threadIdx.x & 31, bg = threadIdx.x >> 5;
    int f = blockIdx.y * 32 + fg;
    double s = 0.0, s2 = 0.0;
    if (f < NN) {
        for (int b = bg; b < BV; b += 16) {
            float v = g_attraw[(size_t)(b * HV + h) * NN + f];
            s += v; s2 += (double)v * v;
        }
    }
    ds[threadIdx.x] = s; ds2[threadIdx.x] = s2;
    __syncthreads();
    if (threadIdx.x < 32 && f < NN) {
        double ts = 0.0, ts2 = 0.0;
        #pragma unroll
        for (int g = 0; g < 16; g++) { ts += ds[fg + 32 * g]; ts2 += ds2[fg + 32 * g]; }
        double mean = ts * (1.0 / BV);
        double var = ts2 * (1.0 / BV) - mean * mean;
        float sc = gamma[h * NN + f] / sqrtf((float)var + 1e-5f);
        g_scale[h * NN + f] = sc;
        g_shift[h * NN + f] = beta[h * NN + f] - (float)mean * sc;
    }
}

// =====================================================================
// kC: affine + column softmax + A assembly
// =====================================================================
__global__ void kC(const float* __restrict__ A_ske, const float* __restrict__ att) {
    __shared__ float sz[NN], cs[NV];
    int h = blockIdx.x, b = blockIdx.y, tid = threadIdx.x;
    const float* raw = g_attraw + (size_t)(b * HV + h) * NN;
    for (int p = tid; p < NN; p += 256)
        sz[p] = fmaf(raw[p], g_scale[h * NN + p], g_shift[h * NN + p]);
    __syncthreads();
    if (tid < NV) {
        int n = tid;
        float mx = -1e30f;
        for (int m = 0; m < NV; m++) mx = fmaxf(mx, sz[m * NV + n]);
        float s = 0.f;
        for (int m = 0; m < NV; m++) { float e = expf(sz[m * NV + n] - mx); sz[m * NV + n] = e; s += e; }
        cs[n] = s;
    }
    __syncthreads();
    float* outp = g_A + (size_t)(b * HV + h) * NN;
    for (int p = tid; p < NN; p += 256) {
        int n = p % NV;
        outp[p] = A_ske[h * NN + p] + att[h * NN + p] + sz[p] / cs[n];
    }
}

// =====================================================================
// kG: per-head: supp = x*A_h, acc += W_h^T supp; f32x2
// grid (256,9), 256 thr, 73.5KB dyn smem, occ 3
// supp phase: exactly 256 slots (1c x 4li x 6j), A-row reuse across li
// =====================================================================
__global__ void __launch_bounds__(256, 3)
kG(const float* __restrict__ mw, const float* __restrict__ mb) {
    extern __shared__ float sm[];
    float* sx   = sm;               // 6272
    float* ssup = sx + 6272;        // 6272
    float* sW   = ssup + 6272;      // 64*65 = 4160
    float* sA2  = sW + 4160;        // 3*23*24 = 1656 (+8) -> 18368 floats
    int b = blockIdx.x, ch = blockIdx.y, tid = threadIdx.x;
    int l0p = ch * AJ;
    const float* xb = g_x2 + (size_t)b * (CVAL * LV * NP);

    for (int i = tid; i < HV * NV * NP; i += 256) {
        int h = i / (NV * NP), r = i - h * (NV * NP), ii = r / NP, j = r - ii * NP;
        sA2[i] = (j < NV) ? g_A[(size_t)b * (HV * NN) + h * NN + ii * NV + j] : 0.f;
    }
    for (int i = tid; i < CVAL * AJ; i += 256) {
        int c = i / AJ, p = i - c * AJ;
        int gp = l0p + p;
        sx[c * AXP + p] = (gp < LV * NP) ? xb[c * (LV * NP) + gp] : 0.f;
    }

    int tr = tid >> 4, tc = tid & 15;
    ull acc2[4][3];
    #pragma unroll
    for (int i = 0; i < 4; i++) {
        int o = tr * 4 + i;
        ull mbs = pk2(mb[o] + mb[64 + o] + mb[128 + o]);
        #pragma unroll
        for (int j = 0; j < 3; j++) acc2[i][j] = mbs;
    }

    int sc = tid & 63, j0 = (tid >> 6) * 6;   // supp slot: c, 6-col group

    for (int h = 0; h < HV; h++) {
        __syncthreads();
        for (int i = tid; i < 4096; i += 256) {
            int o = i >> 6, c = i & 63;
            sW[c * 65 + o] = mw[h * 4096 + i];
        }
        // supp: each thread computes rows (sc) cols [li*24+j0, +6) for all 4 li
        {
            ull a2[4][3];
            #pragma unroll
            for (int li = 0; li < 4; li++)
                #pragma unroll
                for (int j = 0; j < 3; j++) a2[li][j] = 0ull;
            const float* Ab = sA2 + h * (NV * NP) + j0;
            const float* xr = sx + sc * AXP;
            for (int i2 = 0; i2 < NV; i2++) {
                const ull* Ar = (const ull*)(Ab + i2 * NP);
                ull b0 = Ar[0], b1 = Ar[1], b2 = Ar[2];
                #pragma unroll
                for (int li = 0; li < 4; li++) {
                    ull pv = pk2(xr[li * NP + i2]);
                    FMA2(a2[li][0], pv, b0);
                    FMA2(a2[li][1], pv, b1);
                    FMA2(a2[li][2], pv, b2);
                }
            }
            #pragma unroll
            for (int li = 0; li < 4; li++) {
                ull* dst = (ull*)(ssup + sc * AXP + li * NP + j0);
                dst[0] = a2[li][0]; dst[1] = a2[li][1]; dst[2] = a2[li][2];
            }
        }
        __syncthreads();
        // head GEMM accumulate: K=64, 4 rows x 3 pairs
        #pragma unroll 4
        for (int k = 0; k < 64; k++) {
            ull pa0 = pk2(sW[k * 65 + tr * 4 + 0]);
            ull pa1 = pk2(sW[k * 65 + tr * 4 + 1]);
            ull pa2 = pk2(sW[k * 65 + tr * 4 + 2]);
            ull pa3 = pk2(sW[k * 65 + tr * 4 + 3]);
            const ull* bp = (const ull*)(ssup + k * AXP + 2 * tc);
            #pragma unroll
            for (int j = 0; j < 3; j++) {
                ull bb = bp[16 * j];
                FMA2(acc2[0][j], pa0, bb);
                FMA2(acc2[1][j], pa1, bb);
                FMA2(acc2[2][j], pa2, bb);
                FMA2(acc2[3][j], pa3, bb);
            }
        }
    }
    // store gcn2 as 64-bit pairs
    #pragma unroll
    for (int jp = 0; jp < 3; jp++) {
        int col = 2 * tc + 32 * jp;
        int li = col / NP, j = col - li * NP;
        int l = ch * ALC + li;
        if (l < LV) {
            #pragma unroll
            for (int i = 0; i < 4; i++) {
                int o = tr * 4 + i;
                *(ull*)&g_gcn2[((size_t)(b * 64 + o) * LV + l) * NP + j] = acc2[i][jp];
            }
        }
    }
}

// =====================================================================
// kT: out[(b,o,j), l'] = sum_l gcn2[(b,o),l,j]*w[l,l'] + bias[l']
// =====================================================================
__global__ void kT(const float* __restrict__ wseq, const float* __restrict__ bias,
                   float* __restrict__ out) {
    extern __shared__ float smT[];
    float* sg = smT;              // 8*840 = 6720
    float* sw = sg + 6720;        // 35*36 = 1260
    float* sb = sw + 1260;        // 40
    float* so = sb + 40;          // 8*805 = 6440 -> 14460 floats
    int tid = threadIdx.x;
    size_t gbase = (size_t)blockIdx.x * (8 * LV * NP);
    for (int i = tid; i < 8 * LV * NP; i += 256) sg[i] = g_gcn2[gbase + i];
    for (int i = tid; i < LV * LV; i += 256) sw[(i / LV) * 36 + (i % LV)] = wseq[i];
    if (tid < LV) sb[tid] = bias[tid];
    __syncthreads();
    if (tid < 240) {
        int pair = tid / 30, r = tid - pair * 30, jg = r / 5, lg = r - jg * 5;
        int j0 = jg * 4, lp0 = lg * 7;
        float a[4][7];
        #pragma unroll
        for (int t = 0; t < 4; t++)
            #pragma unroll
            for (int u = 0; u < 7; u++) a[t][u] = sb[lp0 + u];
        const float* gp = sg + pair * (LV * NP) + j0;
        #pragma unroll 5
        for (int l = 0; l < LV; l++) {
            float g0 = gp[l * NP + 0], g1 = gp[l * NP + 1], g2 = gp[l * NP + 2], g3 = gp[l * NP + 3];
            const float* wr = sw + l * 36 + lp0;
            #pragma unroll
            for (int u = 0; u < 7; u++) {
                float w = wr[u];
                a[0][u] = fmaf(g0, w, a[0][u]);
                a[1][u] = fmaf(g1, w, a[1][u]);
                a[2][u] = fmaf(g2, w, a[2][u]);
                a[3][u] = fmaf(g3, w, a[3][u]);
            }
        }
        #pragma unroll
        for (int t = 0; t < 4; t++) {
            int jj = j0 + t;
            if (jj < NV) {
                #pragma unroll
                for (int u = 0; u < 7; u++)
                    so[pair * 805 + jj * LV + lp0 + u] = a[t][u];
            }
        }
    }
    __syncthreads();
    size_t obase = (size_t)blockIdx.x * (8 * 805);
    for (int i = tid; i < 8 * 805; i += 256) out[obase + i] = so[i];
}

extern "C" void kernel_launch(void* const* d_in, const int* in_sizes, int n_in,
                              void* d_out, int out_size) {
    const float* x     = (const float*)d_in[0];
    const float* cw1   = (const float*)d_in[1];
    const float* cb1   = (const float*)d_in[2];
    const float* cw2   = (const float*)d_in[3];
    const float* cb2   = (const float*)d_in[4];
    const float* gamma = (const float*)d_in[5];
    const float* beta  = (const float*)d_in[6];
    const float* mw    = (const float*)d_in[7];
    const float* mb    = (const float*)d_in[8];
    const float* att   = (const float*)d_in[9];
    const float* A_ske = (const float*)d_in[10];
    const float* wseq  = (const float*)d_in[11];
    const float* bias  = (const float*)d_in[12];
    float* out = (float*)d_out;

    static bool attr_done = false;
    if (!attr_done) {
        cudaFuncSetAttribute(kA, cudaFuncAttributeMaxDynamicSharedMemorySize, 18240 * 4);
        cudaFuncSetAttribute(kG, cudaFuncAttributeMaxDynamicSharedMemorySize, 18368 * 4);
        cudaFuncSetAttribute(kT, cudaFuncAttributeMaxDynamicSharedMemorySize, 14460 * 4);
        attr_done = true;
    }

    kX<<<2048, 256>>>(x);
    kP<<<dim3(HV, 8), 256>>>(cw1, cb1, cw2, cb2);
    kA<<<dim3(HV, BV), 256, 18240 * 4>>>();
    kB<<<dim3(HV, 17), 512>>>(gamma, beta);
    kC<<<dim3(HV, BV), 256>>>(A_ske, att);
    kG<<<dim3(BV, ANCH), 256, 18368 * 4>>>(mw, mb);
    kT<<<2048, 256, 14460 * 4>>>(wseq, bias, out);
}